// round 14
// baseline (speedup 1.0000x reference)
#include <cuda_runtime.h>
#include <cuda_fp16.h>
#include <math.h>

#define INV_SCALE 0.35355339059327373f
#define C_CH 28
#define C_PAD 32     // padded channel stride (64 B) for aligned uint4 gathers
#define NBINS 4096   // 16x16x16 bins of 8x8x8 voxels
#define MAXPTS 1100000

// Scratch (alloc-free rule: __device__ globals)
__device__ float  g_vol0[C_CH * 32 * 32 * 32];
__device__ float  g_vol1[C_CH * 64 * 64 * 64];
__device__ __half g_vol2[128 * 128 * 128 * C_PAD];   // channel-LAST [z][y][x][c_pad], fp16
__device__ int    g_hist[NBINS];
__device__ int    g_cursor[NBINS];
__device__ float4 g_tmp[MAXPTS];      // {px,py,pz, idx-as-float-bits}
__device__ int    g_binid[MAXPTS];
__device__ float4 g_sorted[MAXPTS];

// 8-point Haar synthesis butterfly. o[p*4+q*2+r] = INV_SCALE * sum (-1)^{up+vq+wr} c_uvw
__device__ __forceinline__ void haar8(float c000, float c001, float c010, float c011,
                                      float c100, float c101, float c110, float c111,
                                      float o[8]) {
    float r0_00 = c000 + c001, r1_00 = c000 - c001;
    float r0_01 = c010 + c011, r1_01 = c010 - c011;
    float r0_10 = c100 + c101, r1_10 = c100 - c101;
    float r0_11 = c110 + c111, r1_11 = c110 - c111;
    float q0r0_0 = r0_00 + r0_01, q1r0_0 = r0_00 - r0_01;
    float q0r1_0 = r1_00 + r1_01, q1r1_0 = r1_00 - r1_01;
    float q0r0_1 = r0_10 + r0_11, q1r0_1 = r0_10 - r0_11;
    float q0r1_1 = r1_10 + r1_11, q1r1_1 = r1_10 - r1_11;
    o[0] = (q0r0_0 + q0r0_1) * INV_SCALE;
    o[1] = (q0r1_0 + q0r1_1) * INV_SCALE;
    o[2] = (q1r0_0 + q1r0_1) * INV_SCALE;
    o[3] = (q1r1_0 + q1r1_1) * INV_SCALE;
    o[4] = (q0r0_0 - q0r0_1) * INV_SCALE;
    o[5] = (q0r1_0 - q0r1_1) * INV_SCALE;
    o[6] = (q1r0_0 - q1r0_1) * INV_SCALE;
    o[7] = (q1r1_0 - q1r1_1) * INV_SCALE;
}

// Channel-first -> channel-first idwt (levels 0, 1). One thread per input cell.
template <int D>
__device__ __forceinline__ void idwt_cf_body(const float* __restrict__ approx,
                                             const float* __restrict__ det,
                                             float* __restrict__ out) {
    const int D3 = D * D * D;
    int tid = blockIdx.x * blockDim.x + threadIdx.x;
    if (tid >= C_CH * D3) return;
    int k = tid % D;
    int j = (tid / D) % D;
    int i = (tid / (D * D)) % D;
    int c = tid / D3;

    float a  = approx[tid];
    float d0 = det[0 * C_CH * D3 + tid];
    float d1 = det[1 * C_CH * D3 + tid];
    float d2 = det[2 * C_CH * D3 + tid];
    float d3 = det[3 * C_CH * D3 + tid];
    float d4 = det[4 * C_CH * D3 + tid];
    float d5 = det[5 * C_CH * D3 + tid];
    float d6 = det[6 * C_CH * D3 + tid];

    float o[8];
    haar8(a, d0, d1, d2, d3, d4, d5, d6, o);

    const int D2 = 2 * D;
    int base = ((c * D2 + 2 * i) * D2 + 2 * j) * D2 + 2 * k;
    out[base]                    = o[0];
    out[base + 1]                = o[1];
    out[base + D2]               = o[2];
    out[base + D2 + 1]           = o[3];
    out[base + D2 * D2]          = o[4];
    out[base + D2 * D2 + 1]      = o[5];
    out[base + D2 * D2 + D2]     = o[6];
    out[base + D2 * D2 + D2 + 1] = o[7];
}

__global__ void idwt_l0(const float* __restrict__ approx, const float* __restrict__ det) {
    idwt_cf_body<16>(approx, det, g_vol0);
}
__global__ void idwt_l1(const float* __restrict__ det) {
    idwt_cf_body<32>(g_vol0, det, g_vol1);
}

// Level 2: channel-first fp32 -> channel-LAST fp16 (padded stride C_PAD).
__global__ void __launch_bounds__(256) idwt_l2(const float* __restrict__ det) {
    __shared__ float sm[8 * C_CH * 33];

    const int j  = blockIdx.x;
    const int i  = blockIdx.y;
    const int k0 = blockIdx.z * 32;
    const int tid = threadIdx.x;

    const int rowbase = i * 64 * 64 + j * 64 + k0;

    for (int r = tid; r < 8 * C_CH * 32; r += 256) {
        int kk  = r & 31;
        int row = r >> 5;
        int s   = row / C_CH;
        int c   = row - s * C_CH;
        const float* src = (s == 0)
            ? (g_vol1 + c * 262144 + rowbase)
            : (det + ((s - 1) * C_CH + c) * 262144 + rowbase);
        sm[row * 33 + kk] = src[kk];
    }
    __syncthreads();

    const int lane = tid & 31;
    const int w    = tid >> 5;
    const int grp  = lane >> 4;
    const int p    = lane & 15;
    if (p < 14) {
        const int c0 = 2 * p;
#pragma unroll
        for (int it = 0; it < 2; it++) {
            int kk = it * 16 + w * 2 + grp;
            float oA[8], oB[8];
            haar8(sm[(0 * C_CH + c0) * 33 + kk], sm[(1 * C_CH + c0) * 33 + kk],
                  sm[(2 * C_CH + c0) * 33 + kk], sm[(3 * C_CH + c0) * 33 + kk],
                  sm[(4 * C_CH + c0) * 33 + kk], sm[(5 * C_CH + c0) * 33 + kk],
                  sm[(6 * C_CH + c0) * 33 + kk], sm[(7 * C_CH + c0) * 33 + kk], oA);
            haar8(sm[(0 * C_CH + c0 + 1) * 33 + kk], sm[(1 * C_CH + c0 + 1) * 33 + kk],
                  sm[(2 * C_CH + c0 + 1) * 33 + kk], sm[(3 * C_CH + c0 + 1) * 33 + kk],
                  sm[(4 * C_CH + c0 + 1) * 33 + kk], sm[(5 * C_CH + c0 + 1) * 33 + kk],
                  sm[(6 * C_CH + c0 + 1) * 33 + kk], sm[(7 * C_CH + c0 + 1) * 33 + kk], oB);

            int X0 = 2 * (k0 + kk);
            int base2 = ((((2 * i) * 128 + (2 * j)) * 128 + X0) * C_PAD + c0) >> 1;
            __half2* v = ((__half2*)g_vol2) + base2;
            const int SP = (128 * 128 * C_PAD) / 2;
            const int SQ = (128 * C_PAD) / 2;
            const int SR = C_PAD / 2;
            v[0]            = __floats2half2_rn(oA[0], oB[0]);
            v[SR]           = __floats2half2_rn(oA[1], oB[1]);
            v[SQ]           = __floats2half2_rn(oA[2], oB[2]);
            v[SQ + SR]      = __floats2half2_rn(oA[3], oB[3]);
            v[SP]           = __floats2half2_rn(oA[4], oB[4]);
            v[SP + SR]      = __floats2half2_rn(oA[5], oB[5]);
            v[SP + SQ]      = __floats2half2_rn(oA[6], oB[6]);
            v[SP + SQ + SR] = __floats2half2_rn(oA[7], oB[7]);
        }
    }
}

// ---- spatial binning of query points (counting sort into 16^3 bins of 8^3 voxels) ----

__global__ void zero_hist() {
    int t = blockIdx.x * blockDim.x + threadIdx.x;
    if (t < NBINS) g_hist[t] = 0;
}

__global__ void bin_count(const float* __restrict__ xyz, int N) {
    int n = blockIdx.x * blockDim.x + threadIdx.x;
    if (n >= N) return;
    float x = xyz[3 * n + 0];
    float y = xyz[3 * n + 1];
    float z = xyz[3 * n + 2];
    const float invb = 1.0f / 1.5f;
    const float half127 = 0.5f * 127.0f;
    float px = (x * invb + 1.0f) * half127;
    float py = (y * invb + 1.0f) * half127;
    float pz = (z * invb + 1.0f) * half127;

    int bx = min(max((int)floorf(px), 0), 127) >> 3;
    int by = min(max((int)floorf(py), 0), 127) >> 3;
    int bz = min(max((int)floorf(pz), 0), 127) >> 3;
    int bin = (bz << 8) | (by << 4) | bx;

    g_tmp[n] = make_float4(px, py, pz, __int_as_float(n));
    g_binid[n] = bin;
    atomicAdd(&g_hist[bin], 1);
}

// Exclusive scan of 4096 bins; one block of 1024 threads, 4 bins/thread.
__global__ void __launch_bounds__(1024) bin_scan() {
    __shared__ int warpsum[32];
    int t = threadIdx.x;
    int v0 = g_hist[4 * t + 0];
    int v1 = g_hist[4 * t + 1];
    int v2 = g_hist[4 * t + 2];
    int v3 = g_hist[4 * t + 3];
    int s = v0 + v1 + v2 + v3;

    int lane = t & 31, wid = t >> 5;
    int inc = s;
#pragma unroll
    for (int o = 1; o < 32; o <<= 1) {
        int u = __shfl_up_sync(0xFFFFFFFFu, inc, o);
        if (lane >= o) inc += u;
    }
    if (lane == 31) warpsum[wid] = inc;
    __syncthreads();
    if (wid == 0) {
        int ws = warpsum[lane];
        int winc = ws;
#pragma unroll
        for (int o = 1; o < 32; o <<= 1) {
            int u = __shfl_up_sync(0xFFFFFFFFu, winc, o);
            if (lane >= o) winc += u;
        }
        warpsum[lane] = winc - ws;   // exclusive warp base
    }
    __syncthreads();
    int excl = warpsum[wid] + (inc - s);
    g_cursor[4 * t + 0] = excl;
    g_cursor[4 * t + 1] = excl + v0;
    g_cursor[4 * t + 2] = excl + v0 + v1;
    g_cursor[4 * t + 3] = excl + v0 + v1 + v2;
}

__global__ void bin_scatter(int N) {
    int n = blockIdx.x * blockDim.x + threadIdx.x;
    if (n >= N) return;
    int bin = g_binid[n];
    int slot = atomicAdd(&g_cursor[bin], 1);
    g_sorted[slot] = g_tmp[n];
}

// ---- query: sorted points, each block handles 512 consecutive points ----
#define QPPB 512

__global__ void __launch_bounds__(128) query_k(float* __restrict__ out, int N) {
    const __half* __restrict__ vp = (const __half*)g_vol2;
    int base = blockIdx.x * QPPB + threadIdx.x;

#pragma unroll 1
    for (int it = 0; it < QPPB / 128; it++) {
        int n = base + it * 128;
        if (n >= N) continue;

        float4 rec = g_sorted[n];
        float px = rec.x, py = rec.y, pz = rec.z;
        int idx = __float_as_int(rec.w);

        float fpx = floorf(px), fpy = floorf(py), fpz = floorf(pz);
        int ix0 = (int)fpx, iy0 = (int)fpy, iz0 = (int)fpz;
        float fx = px - fpx, fy = py - fpy, fz = pz - fpz;

        float acc[C_CH];
#pragma unroll
        for (int c = 0; c < C_CH; c++) acc[c] = 0.0f;

#pragma unroll
        for (int dz = 0; dz < 2; dz++) {
            int iz = iz0 + dz;
            float wz = dz ? fz : (1.0f - fz);
            bool vz = (iz >= 0) & (iz < 128);
            int izc = min(max(iz, 0), 127);
#pragma unroll
            for (int dy = 0; dy < 2; dy++) {
                int iy = iy0 + dy;
                float wy = dy ? fy : (1.0f - fy);
                bool vy = (iy >= 0) & (iy < 128);
                int iyc = min(max(iy, 0), 127);
#pragma unroll
                for (int dx = 0; dx < 2; dx++) {
                    int ix = ix0 + dx;
                    float wx = dx ? fx : (1.0f - fx);
                    bool vx = (ix >= 0) & (ix < 128);
                    int ixc = min(max(ix, 0), 127);

                    float wgt = wx * wy * wz;
                    wgt = (vx & vy & vz) ? wgt : 0.0f;

                    const uint4* p =
                        (const uint4*)(vp + ((izc * 128 + iyc) * 128 + ixc) * C_PAD);
                    uint4 v0 = p[0];
                    uint4 v1 = p[1];
                    uint4 v2 = p[2];
                    uint4 v3 = p[3];

                    float2 a0 = __half22float2(*(const __half2*)&v0.x);
                    float2 a1 = __half22float2(*(const __half2*)&v0.y);
                    float2 a2 = __half22float2(*(const __half2*)&v0.z);
                    float2 a3 = __half22float2(*(const __half2*)&v0.w);
                    acc[0]  = fmaf(wgt, a0.x, acc[0]);   acc[1]  = fmaf(wgt, a0.y, acc[1]);
                    acc[2]  = fmaf(wgt, a1.x, acc[2]);   acc[3]  = fmaf(wgt, a1.y, acc[3]);
                    acc[4]  = fmaf(wgt, a2.x, acc[4]);   acc[5]  = fmaf(wgt, a2.y, acc[5]);
                    acc[6]  = fmaf(wgt, a3.x, acc[6]);   acc[7]  = fmaf(wgt, a3.y, acc[7]);

                    float2 b0 = __half22float2(*(const __half2*)&v1.x);
                    float2 b1 = __half22float2(*(const __half2*)&v1.y);
                    float2 b2 = __half22float2(*(const __half2*)&v1.z);
                    float2 b3 = __half22float2(*(const __half2*)&v1.w);
                    acc[8]  = fmaf(wgt, b0.x, acc[8]);   acc[9]  = fmaf(wgt, b0.y, acc[9]);
                    acc[10] = fmaf(wgt, b1.x, acc[10]);  acc[11] = fmaf(wgt, b1.y, acc[11]);
                    acc[12] = fmaf(wgt, b2.x, acc[12]);  acc[13] = fmaf(wgt, b2.y, acc[13]);
                    acc[14] = fmaf(wgt, b3.x, acc[14]);  acc[15] = fmaf(wgt, b3.y, acc[15]);

                    float2 c0 = __half22float2(*(const __half2*)&v2.x);
                    float2 c1 = __half22float2(*(const __half2*)&v2.y);
                    float2 c2 = __half22float2(*(const __half2*)&v2.z);
                    float2 c3 = __half22float2(*(const __half2*)&v2.w);
                    acc[16] = fmaf(wgt, c0.x, acc[16]);  acc[17] = fmaf(wgt, c0.y, acc[17]);
                    acc[18] = fmaf(wgt, c1.x, acc[18]);  acc[19] = fmaf(wgt, c1.y, acc[19]);
                    acc[20] = fmaf(wgt, c2.x, acc[20]);  acc[21] = fmaf(wgt, c2.y, acc[21]);
                    acc[22] = fmaf(wgt, c3.x, acc[22]);  acc[23] = fmaf(wgt, c3.y, acc[23]);

                    float2 d0 = __half22float2(*(const __half2*)&v3.x);
                    float2 d1 = __half22float2(*(const __half2*)&v3.y);
                    acc[24] = fmaf(wgt, d0.x, acc[24]);  acc[25] = fmaf(wgt, d0.y, acc[25]);
                    acc[26] = fmaf(wgt, d1.x, acc[26]);  acc[27] = fmaf(wgt, d1.y, acc[27]);
                }
            }
        }

        float4* po = (float4*)(out + (long)idx * C_CH);
#pragma unroll
        for (int t = 0; t < 7; t++) {
            po[t] = make_float4(acc[4 * t + 0], acc[4 * t + 1],
                                acc[4 * t + 2], acc[4 * t + 3]);
        }
    }
}

extern "C" void kernel_launch(void* const* d_in, const int* in_sizes, int n_in,
                              void* d_out, int out_size) {
    const float* approx    = (const float*)d_in[0];   // (28,16,16,16)
    const float* details_0 = (const float*)d_in[1];   // (7,28,16,16,16)
    const float* details_1 = (const float*)d_in[2];   // (7,28,32,32,32)
    const float* details_2 = (const float*)d_in[3];   // (7,28,64,64,64)
    const float* xyz       = (const float*)d_in[4];   // (N,3)
    float* out = (float*)d_out;

    int N = in_sizes[4] / 3;

    // IDWT pyramid
    idwt_l0<<<(C_CH * 4096 + 255) / 256, 256>>>(approx, details_0);
    idwt_l1<<<(C_CH * 32768 + 255) / 256, 256>>>(details_1);
    dim3 g2(64, 64, 2);
    idwt_l2<<<g2, 256>>>(details_2);

    // Spatial binning of query points
    zero_hist<<<(NBINS + 255) / 256, 256>>>();
    bin_count<<<(N + 255) / 256, 256>>>(xyz, N);
    bin_scan<<<1, 1024>>>();
    bin_scatter<<<(N + 255) / 256, 256>>>(N);

    // Query in sorted order
    query_k<<<(N + QPPB - 1) / QPPB, 128>>>(out, N);
}